// round 17
// baseline (speedup 1.0000x reference)
#include <cuda_runtime.h>

#define BATCH 16
#define CH    256
#define IH    100
#define IW    100
#define NBOX  100
#define RH    40
#define RW    40
#define NCLS  599

// Scratch (no allocations allowed)
__device__ float g_pooled[BATCH * NBOX * CH];   // [B][N][C]  (coalesced reads in k2)
__device__ int2  g_seg[BATCH * NCLS];           // per-class (start, end) into g_list
__device__ int   g_list[BATCH * NBOX];          // box idx sorted by class (asc n within)

// Quantize one box (xyxy, image coords) to the 40x40 grid. Matches
// jnp.round (half-to-even) + clip semantics of the reference.
__device__ __forceinline__ int quantize_box(float4 bb, bool& valid) {
    const float s = 40.0f / 1024.0f;            // exact in fp32
    int x1 = max((int)rintf(bb.x * s), 0);
    int y1 = max((int)rintf(bb.y * s), 0);
    int x2 = min((int)rintf(bb.z * s), RW);
    int y2 = min((int)rintf(bb.w * s), RH);
    valid = (x1 < x2) && (y1 < y2);
    x1 = min(max(x1, 0), RW);  x2 = min(max(x2, 0), RW);
    y1 = min(max(y1, 0), RH);  y2 = min(max(y2, 0), RH);
    return x1 | (y1 << 8) | (x2 << 16) | (y2 << 24);
}

// ---------------------------------------------------------------------------
// Kernel 1 (CPB=1): one (b, channel) plane per CTA — 4096 CTAs for maximum
// latency overlap. Bilinear 100->40 resize into smem (streaming __ldcs —
// strictly single-use data; integer-exact taps), one barrier, then direct
// box-sum pooling with direct scalar store into [B][N][C]. The c==0 CTA of
// each batch also counting-sorts boxes by class into g_seg / g_list
// (deterministic, ascending-n within each class).
// ---------------------------------------------------------------------------
__global__ __launch_bounds__(256) void resize_pool_kernel(
        const float* __restrict__ feat, const float* __restrict__ boxes,
        const int* __restrict__ gt) {
    __shared__ float res[RH * RW];              // 6.4 KB
    __shared__ int   s_box[NBOX];               // packed x1,y1,x2,y2 (0 if invalid)
    __shared__ int   s_cls[NBOX];               // valid ? cls : -1 (meta CTA)
    __shared__ int   s_cnt[NCLS];               // histogram -> offsets (meta CTA)
    __shared__ int   s_blk[20];

    const int blk = blockIdx.x;                 // 0 .. BATCH*CH-1
    const int b   = blk / CH;
    const int c   = blk % CH;
    const int tid = threadIdx.x;
    const bool meta = (c == 0);                 // uniform across CTA

    // --- quantize this batch's boxes (threads 0..99) ---
    bool v_me = false;
    if (tid < NBOX) {
        float4 bb = __ldg((const float4*)boxes + b * NBOX + tid);
        int pk = quantize_box(bb, v_me);
        s_box[tid] = v_me ? pk : 0;             // invalid -> x1==x2==0
        if (meta) {
            int cls = __ldg(gt + b * NBOX + tid);
            s_cls[tid] = v_me ? cls : -1;
        }
    }

    // --- bilinear resize: src = 2.5*dst + 0.75 -> integer-exact taps:
    //     t0 = (5*t+1)>>1 ; frac = t odd ? 0.25 : 0.75 (bit-identical) ---
    const float* __restrict__ in = feat + (size_t)(b * CH + c) * (IH * IW);
    for (int i = tid; i < RH * RW; i += 256) {
        int oy = i / RW, ox = i % RW;
        int y0 = (5 * oy + 1) >> 1;
        int x0 = (5 * ox + 1) >> 1;
        float fy = (oy & 1) ? 0.25f : 0.75f;
        float fx = (ox & 1) ? 0.25f : 0.75f;
        int off = y0 * IW + x0;
        float gx0 = 1.0f - fx, gy0 = 1.0f - fy;
        float v00 = __ldcs(in + off),      v01 = __ldcs(in + off + 1);
        float v10 = __ldcs(in + off + IW), v11 = __ldcs(in + off + IW + 1);
        res[i] = gy0 * (gx0 * v00 + fx * v01) + fy * (gx0 * v10 + fx * v11);
    }
    __syncthreads();

    // --- direct box-average pooling + direct store: thread = box ---
    if (tid < NBOX) {
        int pk = s_box[tid];
        int x1 = pk & 0xFF, y1 = (pk >> 8) & 0xFF;
        int x2 = (pk >> 16) & 0xFF, y2 = (pk >> 24) & 0xFF;
        float out = 0.0f;
        if (x1 < x2) {                          // valid (invalid stored as 0)
            float s = 0.0f;
            for (int y = y1; y < y2; y++) {
                float rs = 0.0f;
                for (int x = x1; x < x2; x++) rs += res[y * RW + x];
                s += rs;
            }
            out = s / (float)((y2 - y1) * (x2 - x1));
        }
        g_pooled[(size_t)(b * NBOX + tid) * CH + c] = out;
    }

    // --- meta CTA only: counting-sort boxes by class (deterministic) ---
    if (meta) {
        for (int i = tid; i < NCLS; i += 256) s_cnt[i] = 0;
        __syncthreads();
        if (tid < NBOX && s_cls[tid] >= 0)
            atomicAdd(&s_cnt[s_cls[tid]], 1);   // histogram
        __syncthreads();
        if (tid < 19) {                          // group sums (19 x 32)
            int s = 0;
            for (int j = 0; j < 32; j++) {
                int cc = tid * 32 + j;
                if (cc < NCLS) s += s_cnt[cc];
            }
            s_blk[tid] = s;
        }
        __syncthreads();
        if (tid == 0) {
            int r = 0;
            for (int w = 0; w < 19; w++) { int t = s_blk[w]; s_blk[w] = r; r += t; }
            s_blk[19] = r;                      // total valid boxes
        }
        __syncthreads();
        if (tid < 19) {
            int r = s_blk[tid];
            for (int j = 0; j < 32; j++) {
                int cc = tid * 32 + j;
                if (cc < NCLS) { int t = s_cnt[cc]; s_cnt[cc] = r; r += t; }
            }
        }
        __syncthreads();
        // per-class (start, end) pairs -> one LDG.64 in kernel 2
        for (int cc = tid; cc < NCLS; cc += 256) {
            int st = s_cnt[cc];
            int en = (cc + 1 < NCLS) ? s_cnt[cc + 1] : s_blk[19];
            g_seg[b * NCLS + cc] = make_int2(st, en);
        }
        // scatter: rank = #{m<n with same class} (deterministic ascending order)
        if (tid < NBOX && s_cls[tid] >= 0) {
            int cc = s_cls[tid];
            int rank = 0;
            for (int m = 0; m < tid; m++) rank += (s_cls[m] == cc);
            g_list[b * NBOX + s_cnt[cc] + rank] = tid;
        }
    }
}

// ---------------------------------------------------------------------------
// Kernel 2 (R16-measured best): scatter-mean, barrier-free. One 64-thread
// group per class (4 per CTA, grid 150x16); thread = float4 channel-quad.
// Single LDG.64 fetches (start,end). Empty class (84%): that load + one
// STG.128 of zeros. Non-empty: walk the presorted g_list segment (ascending
// n == segment_sum order) with float4 gathers.
// ---------------------------------------------------------------------------
__global__ __launch_bounds__(256) void class_mean_kernel(float* __restrict__ out) {
    const int t   = threadIdx.x;
    const int cls = blockIdx.x * 4 + (t >> 6);   // class for this 64-thread group
    const int q   = t & 63;                      // channel quad 0..63
    const int b   = blockIdx.y;
    if (cls >= NCLS) return;

    int2 se = __ldg(&g_seg[b * NCLS + cls]);     // one 8B broadcast load
    int st = se.x, en = se.y;

    float4 acc = make_float4(0.0f, 0.0f, 0.0f, 0.0f);
    if (en > st) {
        const float4* __restrict__ pool =
            (const float4*)(g_pooled + (size_t)b * NBOX * CH) + q;
        for (int k = st; k < en; k++) {          // ascending n within class
            int n = __ldg(&g_list[b * NBOX + k]);
            float4 v = __ldg(pool + (size_t)n * (CH / 4));
            acc.x += v.x;  acc.y += v.y;  acc.z += v.z;  acc.w += v.w;
        }
        float inv = 1.0f / (float)(en - st);
        acc.x *= inv;  acc.y *= inv;  acc.z *= inv;  acc.w *= inv;
    }
    ((float4*)(out + (size_t)(b * NCLS + cls) * CH))[q] = acc;
}

// ---------------------------------------------------------------------------
extern "C" void kernel_launch(void* const* d_in, const int* in_sizes, int n_in,
                              void* d_out, int out_size) {
    const float* feat  = (const float*)d_in[0];   // [16,256,100,100] f32
    const float* boxes = (const float*)d_in[1];   // [16,100,4] f32
    const int*   gt    = (const int*)d_in[2];     // [16,100] i32
    float* out = (float*)d_out;                   // [16,599,256] f32

    resize_pool_kernel<<<BATCH * CH, 256>>>(feat, boxes, gt);
    dim3 g2((NCLS + 3) / 4, BATCH);               // 150 x 16
    class_mean_kernel<<<g2, 256>>>(out);
}